// round 13
// baseline (speedup 1.0000x reference)
#include <cuda_runtime.h>
#include <cuda_fp16.h>
#include <math.h>
#include <stdint.h>

typedef unsigned long long u64;
typedef unsigned int u32;

// Problem constants
#define NROWS 262144
#define DX 64
#define DZ 32
#define NB 1024
#define TR 256
#define GRID_MAIN (NROWS / TR)   // 1024
#define NCHUNK 128               // 1024 cols / 8
#define SZP 34                   // s_zf row stride (floats)

// Scratch globals
// Codebook B fragments (fp16-quantized v, HMMA m16n8k16 layout):
// [chunk 128][ktile 2][lane 32][reg 2] u32   (64 KB)
__device__ u32    g_bfrag[NCHUNK * 2 * 32 * 2];
// W_enc fragments fp16: [(kt*4+nt)*2+term][lane] ; term 0=hi 1=lo
__device__ uint2  g_wef[4 * 4 * 2 * 32];
// W_dec fragments fp16: [(kt*8+nt)*2+term][lane]
__device__ uint2  g_wdf[2 * 8 * 2 * 32];
__device__ float  g_hn[NB];            // 0.5*||fp16(v)||^2 (consistent w/ B)
__device__ float  g_sum[NB * DZ];      // global sum_z accumulator
__device__ float  g_cnt[NB];           // global count accumulator
__device__ unsigned char g_code[NB];
__device__ int    g_midx;
__device__ double g_recon;
__device__ double g_commit;

// pack two floats -> fp16x2 u32 (first element in low half)
__device__ __forceinline__ u32 pack_hf2(float f0, float f1) {
    __half2 h = __floats2half2_rn(f0, f1);
    return *(u32*)&h;
}
__device__ __forceinline__ float hf_hi(float f) {
    return __half2float(__float2half_rn(f));
}
__device__ __forceinline__ u32 pack_hlo2(float f0, float f1) {
    return pack_hf2(f0 - hf_hi(f0), f1 - hf_hi(f1));
}
// B-fragment load, L1-sticky
__device__ __forceinline__ uint2 ldg_b(const uint2* p) {
    uint2 v;
    asm volatile("ld.global.nc.L1::evict_last.v2.u32 {%0,%1}, [%2];"
                 : "=r"(v.x), "=r"(v.y) : "l"(p));
    return v;
}

#define MMA_F16(d, a, b) \
    asm volatile( \
        "mma.sync.aligned.m16n8k16.row.col.f32.f16.f16.f32 " \
        "{%0,%1,%2,%3},{%4,%5,%6,%7},{%8,%9},{%0,%1,%2,%3};" \
        : "+f"(d[0]), "+f"(d[1]), "+f"(d[2]), "+f"(d[3]) \
        : "r"(a[0]), "r"(a[1]), "r"(a[2]), "r"(a[3]), "r"(b[0]), "r"(b[1]))

// ---------------------------------------------------------------------------
// init: codebook/W fragments (fp16), hn on quantized codebook, zero accums.
// 32768 threads.
// ---------------------------------------------------------------------------
__global__ void k_init(const float* __restrict__ vectors,
                       const float* __restrict__ W_enc,
                       const float* __restrict__ W_dec) {
    int t = blockIdx.x * blockDim.x + threadIdx.x;  // 0..32767

    if (t < NCHUNK * 2 * 32) {           // codebook fragment (v_hi only)
        int lane  = t & 31;
        int tile  = (t >> 5) & 1;
        int chunk = t >> 6;
        int n  = chunk * 8 + (lane >> 2);
        int tt = lane & 3;
        int kbase = tile * 16 + 2 * tt;
        const float* vr = vectors + (size_t)n * DZ;
        g_bfrag[t * 2]     = pack_hf2(vr[kbase],     vr[kbase + 1]);
        g_bfrag[t * 2 + 1] = pack_hf2(vr[kbase + 8], vr[kbase + 9]);
    } else if (t < 8192 + 1024) {        // W_enc fragment
        int e = t - 8192;
        int lane = e & 31, term = (e >> 5) & 1, nt = (e >> 6) & 3, kt = e >> 8;
        int n = nt * 8 + (lane >> 2);
        int k = kt * 16 + 2 * (lane & 3);
        float a0 = W_enc[k * DZ + n],       a1 = W_enc[(k + 1) * DZ + n];
        float b0 = W_enc[(k + 8) * DZ + n], b1 = W_enc[(k + 9) * DZ + n];
        uint2 v;
        if (term == 0) { v.x = pack_hf2(a0, a1);  v.y = pack_hf2(b0, b1); }
        else           { v.x = pack_hlo2(a0, a1); v.y = pack_hlo2(b0, b1); }
        g_wef[e] = v;
    } else if (t < 8192 + 1024 + 2048) { // W_dec fragment
        int e = t - 8192 - 1024;
        int lane = e & 31, term = (e >> 5) & 1, nt = (e >> 6) & 7, kt = e >> 9;
        int n = nt * 8 + (lane >> 2);
        int k = kt * 16 + 2 * (lane & 3);
        float a0 = W_dec[k * DX + n],       a1 = W_dec[(k + 1) * DX + n];
        float b0 = W_dec[(k + 8) * DX + n], b1 = W_dec[(k + 9) * DX + n];
        uint2 v;
        if (term == 0) { v.x = pack_hf2(a0, a1);  v.y = pack_hf2(b0, b1); }
        else           { v.x = pack_hlo2(a0, a1); v.y = pack_hlo2(b0, b1); }
        g_wdf[e] = v;
    }

    g_sum[t] = 0.f;
    if (t < NB) {
        float s = 0.f;
#pragma unroll
        for (int d = 0; d < DZ; ++d) {
            float v = hf_hi(vectors[t * DZ + d]);   // quantized, matches B
            s = fmaf(v, v, s);
        }
        g_hn[t] = 0.5f * s;
        g_cnt[t] = 0.f;
    }
    if (t == 0) { g_recon = 0.0; g_commit = 0.0; }
}

// ---------------------------------------------------------------------------
// main fused kernel: 256 rows/CTA, each warp 32 rows (two m16 tiles).
// fp16 encoder MMA (3-term) -> fp16 scores MMA (z 2-term, v 1-term,
// consistent hn) -> argmin -> gather/atomics -> fp16 decoder MMA (3-term)
// -> losses.  256 threads, 2 CTAs/SM.  (Known-good R9 configuration.)
// ---------------------------------------------------------------------------
// smem float offsets:
#define SM_ZF   0                      // [256][34] 8704 (z, then q overlay)
#define SM_HN   8704                   // 1024
#define SM_BENC 9728                   // 32
#define SM_BDEC 9760                   // 64
#define SM_RIDX 9824                   // 256 (int)
#define SM_RED  10080                  // 16
#define SM_TOTAL_FLOATS 10096
#define SMEM_MAIN (SM_TOTAL_FLOATS * 4)

__global__ void __launch_bounds__(256, 2) k_main(
    const float* __restrict__ x, const float* __restrict__ b_enc,
    const float* __restrict__ vectors, const float* __restrict__ b_dec)
{
    extern __shared__ float sm[];
    float* s_zf   = sm + SM_ZF;
    float* s_hn   = sm + SM_HN;
    float* s_benc = sm + SM_BENC;
    float* s_bdec = sm + SM_BDEC;
    int*   s_ridx = (int*)(sm + SM_RIDX);
    float* s_red  = sm + SM_RED;

    const int tid  = threadIdx.x;
    const int wid  = tid >> 5;
    const int lane = tid & 31;
    const int g4   = lane >> 2;
    const int t4   = lane & 3;
    const int row0 = blockIdx.x * TR;
    const unsigned FULL = 0xFFFFFFFFu;

    // ---- biases + hn into smem ----
    for (int n = tid; n < NB; n += 256) s_hn[n] = g_hn[n];
    if (tid < DZ) s_benc[tid] = b_enc[tid];
    if (tid < DX) s_bdec[tid] = b_dec[tid];
    __syncthreads();

    // ---- encoder (per tile): z = x @ W_enc + b_enc via fp16 HMMA (3-term);
    //      scores A-fragments (fp16 hi/lo of z) built straight from regs ----
    u32 Ahi[2][2][4], Alo[2][2][4];   // [tile][kt][frag]
#pragma unroll
    for (int tile = 0; tile < 2; ++tile) {
        const int r0 = wid * 32 + tile * 16 + g4;
        const int r1 = r0 + 8;
        const float2* px0 = (const float2*)(x + (size_t)(row0 + r0) * DX);
        const float2* px1 = (const float2*)(x + (size_t)(row0 + r1) * DX);

        u32 XAhi[4][4], XAlo[4][4];
#pragma unroll
        for (int kt = 0; kt < 4; ++kt) {
            int i0 = kt * 8 + t4;
            float2 x00 = px0[i0],     x10 = px1[i0];
            float2 x01 = px0[i0 + 4], x11 = px1[i0 + 4];
            XAhi[kt][0] = pack_hf2(x00.x, x00.y);
            XAhi[kt][1] = pack_hf2(x10.x, x10.y);
            XAhi[kt][2] = pack_hf2(x01.x, x01.y);
            XAhi[kt][3] = pack_hf2(x11.x, x11.y);
            XAlo[kt][0] = pack_hlo2(x00.x, x00.y);
            XAlo[kt][1] = pack_hlo2(x10.x, x10.y);
            XAlo[kt][2] = pack_hlo2(x01.x, x01.y);
            XAlo[kt][3] = pack_hlo2(x11.x, x11.y);
        }

        float zr[4][4];
#pragma unroll
        for (int nt = 0; nt < 4; ++nt) {
            int c0 = nt * 8 + 2 * t4;
            float2 be = *(const float2*)(s_benc + c0);
            float da[4] = {be.x, be.y, be.x, be.y};
            float db[4] = {0.f, 0.f, 0.f, 0.f};
#pragma unroll
            for (int kt = 0; kt < 4; ++kt) {
                uint2 bh = g_wef[((kt * 4 + nt) * 2 + 0) * 32 + lane];
                uint2 bl = g_wef[((kt * 4 + nt) * 2 + 1) * 32 + lane];
                u32 BH[2] = {bh.x, bh.y};
                u32 BL[2] = {bl.x, bl.y};
                if (kt & 1) {
                    MMA_F16(db, XAhi[kt], BH);
                    MMA_F16(da, XAhi[kt], BL);
                    MMA_F16(db, XAlo[kt], BH);
                } else {
                    MMA_F16(da, XAhi[kt], BH);
                    MMA_F16(db, XAhi[kt], BL);
                    MMA_F16(da, XAlo[kt], BH);
                }
            }
#pragma unroll
            for (int i = 0; i < 4; ++i) zr[nt][i] = da[i] + db[i];
            *(float2*)(s_zf + r0 * SZP + c0) = make_float2(zr[nt][0], zr[nt][1]);
            *(float2*)(s_zf + r1 * SZP + c0) = make_float2(zr[nt][2], zr[nt][3]);
        }

        // scores A fragments (fp16 hi/lo of z): kt=0 <- nt0,1 ; kt=1 <- nt2,3
#pragma unroll
        for (int kt = 0; kt < 2; ++kt) {
            int n0 = kt * 2, n1 = kt * 2 + 1;
            Ahi[tile][kt][0] = pack_hf2(zr[n0][0], zr[n0][1]);
            Ahi[tile][kt][1] = pack_hf2(zr[n0][2], zr[n0][3]);
            Ahi[tile][kt][2] = pack_hf2(zr[n1][0], zr[n1][1]);
            Ahi[tile][kt][3] = pack_hf2(zr[n1][2], zr[n1][3]);
            Alo[tile][kt][0] = pack_hlo2(zr[n0][0], zr[n0][1]);
            Alo[tile][kt][1] = pack_hlo2(zr[n0][2], zr[n0][3]);
            Alo[tile][kt][2] = pack_hlo2(zr[n1][0], zr[n1][1]);
            Alo[tile][kt][3] = pack_hlo2(zr[n1][2], zr[n1][3]);
        }
    }
    __syncthreads();   // z visible block-wide (gather reads it later)

    // ---- scores: 8 HMMA per chunk (v 1-term, z 2-term, B reused) ----
    float best[4] = {-3.4e38f, -3.4e38f, -3.4e38f, -3.4e38f};
    int   bidx[4] = {0, 0, 0, 0};
    const uint2* bsrc = (const uint2*)g_bfrag + lane;

    uint2 n0 = ldg_b(bsrc), n1 = ldg_b(bsrc + 32);
    float2 hnv = *(const float2*)(s_hn + 2 * t4);

#pragma unroll 4
    for (int c = 0; c < NCHUNK; ++c) {
        u32 B0[2] = {n0.x, n0.y};
        u32 B1[2] = {n1.x, n1.y};
        float2 hn = hnv;
        if (c + 1 < NCHUNK) {
            const uint2* np = bsrc + (c + 1) * 64;
            n0 = ldg_b(np); n1 = ldg_b(np + 32);
            hnv = *(const float2*)(s_hn + (c + 1) * 8 + 2 * t4);
        }

        float da0[4] = {-hn.x, -hn.y, -hn.x, -hn.y};
        float db0[4] = {0.f, 0.f, 0.f, 0.f};
        float da1[4] = {-hn.x, -hn.y, -hn.x, -hn.y};
        float db1[4] = {0.f, 0.f, 0.f, 0.f};
        MMA_F16(da0, Ahi[0][0], B0);
        MMA_F16(db0, Ahi[0][1], B1);
        MMA_F16(da1, Ahi[1][0], B0);
        MMA_F16(db1, Ahi[1][1], B1);
        MMA_F16(da0, Alo[0][0], B0);
        MMA_F16(db0, Alo[0][1], B1);
        MMA_F16(da1, Alo[1][0], B0);
        MMA_F16(db1, Alo[1][1], B1);

        int col0 = c * 8 + 2 * t4;
#pragma unroll
        for (int tile = 0; tile < 2; ++tile) {
            const float* da = tile ? da1 : da0;
            const float* db = tile ? db1 : db0;
            float s0 = da[0] + db[0];
            float s1 = da[1] + db[1];
            float s2 = da[2] + db[2];
            float s3 = da[3] + db[3];
            bool c0 = s1 > s0;
            float v0 = c0 ? s1 : s0; int i0 = col0 + (int)c0;
            bool c1 = s3 > s2;
            float v1 = c1 ? s3 : s2; int i1 = col0 + (int)c1;
            if (v0 > best[tile * 2])     { best[tile * 2] = v0;     bidx[tile * 2] = i0; }
            if (v1 > best[tile * 2 + 1]) { best[tile * 2 + 1] = v1; bidx[tile * 2 + 1] = i1; }
        }
    }

    // ---- quad reduce (lanes sharing rows), lowest index on ties ----
#pragma unroll
    for (int i = 0; i < 4; ++i) {
        float bs = best[i]; int bi = bidx[i];
#pragma unroll
        for (int off = 1; off <= 2; off <<= 1) {
            float ob = __shfl_xor_sync(FULL, bs, off);
            int   oi = __shfl_xor_sync(FULL, bi, off);
            if (ob > bs || (ob == bs && oi < bi)) { bs = ob; bi = oi; }
        }
        if (t4 == 0) {
            int tile = i >> 1, half = i & 1;
            s_ridx[wid * 32 + tile * 16 + half * 8 + g4] = bi;
        }
    }
    __syncthreads();

    // ---- gather q + commitment + segment-sum atomics (z then q overlay) ---
    float commit = 0.f;
    {
        const int col = lane;
        const int rbg = wid * 32;
#pragma unroll
        for (int rr = 0; rr < 32; ++rr) {
            int r = rbg + rr;
            int b = s_ridx[r];
            float zz = s_zf[r * SZP + col];
            float q = vectors[(size_t)b * DZ + col];
            s_zf[r * SZP + col] = q;   // same thread, same address: overlay OK
            float df = q - zz;
            commit = fmaf(df, df, commit);
            atomicAdd(&g_sum[b * DZ + col], zz);
            if (col == 0) atomicAdd(&g_cnt[b], 1.f);
        }
    }
    __syncthreads();  // q complete block-wide

    // ---- decoder (per tile): mu = q @ W_dec + b_dec via fp16 HMMA; recon --
    float recon = 0.f;
#pragma unroll
    for (int tile = 0; tile < 2; ++tile) {
        const int r0 = wid * 32 + tile * 16 + g4;
        const int r1 = r0 + 8;
        const float2* px0 = (const float2*)(x + (size_t)(row0 + r0) * DX);
        const float2* px1 = (const float2*)(x + (size_t)(row0 + r1) * DX);

        u32 QAhi[2][4], QAlo[2][4];
#pragma unroll
        for (int kt = 0; kt < 2; ++kt) {
            int kb = kt * 16 + 2 * t4;
            float2 q00 = *(const float2*)(s_zf + r0 * SZP + kb);
            float2 q10 = *(const float2*)(s_zf + r1 * SZP + kb);
            float2 q01 = *(const float2*)(s_zf + r0 * SZP + kb + 8);
            float2 q11 = *(const float2*)(s_zf + r1 * SZP + kb + 8);
            QAhi[kt][0] = pack_hf2(q00.x, q00.y);
            QAhi[kt][1] = pack_hf2(q10.x, q10.y);
            QAhi[kt][2] = pack_hf2(q01.x, q01.y);
            QAhi[kt][3] = pack_hf2(q11.x, q11.y);
            QAlo[kt][0] = pack_hlo2(q00.x, q00.y);
            QAlo[kt][1] = pack_hlo2(q10.x, q10.y);
            QAlo[kt][2] = pack_hlo2(q01.x, q01.y);
            QAlo[kt][3] = pack_hlo2(q11.x, q11.y);
        }

#pragma unroll
        for (int nt = 0; nt < 8; ++nt) {
            int c0 = nt * 8 + 2 * t4;
            float2 bd = *(const float2*)(s_bdec + c0);
            float da[4] = {bd.x, bd.y, bd.x, bd.y};
            float db[4] = {0.f, 0.f, 0.f, 0.f};
#pragma unroll
            for (int kt = 0; kt < 2; ++kt) {
                uint2 bh = g_wdf[((kt * 8 + nt) * 2 + 0) * 32 + lane];
                uint2 bl = g_wdf[((kt * 8 + nt) * 2 + 1) * 32 + lane];
                u32 BH[2] = {bh.x, bh.y};
                u32 BL[2] = {bl.x, bl.y};
                if (kt) {
                    MMA_F16(db, QAhi[kt], BH);
                    MMA_F16(da, QAhi[kt], BL);
                    MMA_F16(db, QAlo[kt], BH);
                } else {
                    MMA_F16(da, QAhi[kt], BH);
                    MMA_F16(db, QAhi[kt], BL);
                    MMA_F16(da, QAlo[kt], BH);
                }
            }
            int i0 = nt * 4 + t4;
            float2 x0 = px0[i0];
            float2 x1 = px1[i0];
            float d0 = x0.x - (da[0] + db[0]);
            float d1 = x0.y - (da[1] + db[1]);
            float d2 = x1.x - (da[2] + db[2]);
            float d3 = x1.y - (da[3] + db[3]);
            recon = fmaf(d0, d0, recon);
            recon = fmaf(d1, d1, recon);
            recon = fmaf(d2, d2, recon);
            recon = fmaf(d3, d3, recon);
        }
    }

    // ---- block reduce losses -> double atomics ----
#pragma unroll
    for (int off = 16; off; off >>= 1) {
        commit += __shfl_xor_sync(FULL, commit, off);
        recon  += __shfl_xor_sync(FULL, recon, off);
    }
    if (lane == 0) { s_red[wid] = commit; s_red[8 + wid] = recon; }
    __syncthreads();
    if (tid == 0) {
        float cs = 0.f, rs = 0.f;
        for (int w = 0; w < 8; w++) { cs += s_red[w]; rs += s_red[8 + w]; }
        atomicAdd(&g_commit, (double)cs);
        atomicAdd(&g_recon,  (double)rs);
    }
}

// ---------------------------------------------------------------------------
// final1: aem, argmax, dead-code scan (fast path when none dead); loss + aem
// ---------------------------------------------------------------------------
__global__ void k_final1(const float* __restrict__ assignments,
                         float* __restrict__ out)
{
    __shared__ float s_aem[NB];
    __shared__ unsigned char s_na[NB];
    __shared__ unsigned char s_code[NB];
    __shared__ float s_rmax[32];
    __shared__ int   s_rmaxi[32];
    __shared__ int   s_maxidx;
    const unsigned FULL = 0xFFFFFFFFu;
    int tid = threadIdx.x;  // 1024 threads, tid == bin

    float c = g_cnt[tid];
    float ba = c * (1.0f / (float)NROWS);
    float aem = 0.99f * assignments[tid] + 0.01f * ba;
    s_aem[tid] = aem;
    int na = (aem * (float)NROWS) < 9.765625e-05f ? 1 : 0;
    s_na[tid] = (unsigned char)na;
    s_code[tid] = 0;

    float mv = c; int mi = tid;
#pragma unroll
    for (int off = 16; off; off >>= 1) {
        float ov = __shfl_xor_sync(FULL, mv, off);
        int   oi = __shfl_xor_sync(FULL, mi, off);
        if (ov > mv || (ov == mv && oi < mi)) { mv = ov; mi = oi; }
    }
    if ((tid & 31) == 0) { s_rmax[tid >> 5] = mv; s_rmaxi[tid >> 5] = mi; }
    int any_na = __syncthreads_or(na);
    if (tid == 0) {
        float m = s_rmax[0]; int midx = s_rmaxi[0];
        for (int w = 1; w < 32; w++) {
            if (s_rmax[w] > m || (s_rmax[w] == m && s_rmaxi[w] < midx)) {
                m = s_rmax[w]; midx = s_rmaxi[w];
            }
        }
        s_maxidx = midx;
        g_midx = midx;
    }
    __syncthreads();

    if (any_na) {
        if (tid == 0) {
            int midx = s_maxidx;
            bool maxRe = false;
            for (int i = NB - 1; i >= 0; --i) {
                if (s_na[i]) {
                    float na2 = s_aem[midx] * 0.5f;
                    s_code[i] = maxRe ? 2 : 1;
                    s_aem[i] = na2;
                    s_aem[midx] = na2;
                    if (i == midx) maxRe = true;
                }
            }
        }
        __syncthreads();
    }

    g_code[tid] = s_code[tid];
    out[1 + NB * DZ + tid] = s_aem[tid];

    if (tid == 0) {
        double recon = 0.5 * (g_recon / (double)NROWS)
                     + 32.0 * 1.8378770664093453;   // 0.5*d_x*log(2*pi)
        double commit = g_commit / ((double)NROWS * (double)DZ);
        out[0] = (float)(recon + 0.25 * commit);
    }
}

// ---------------------------------------------------------------------------
// final2: new_vectors (parallel, 32 blocks x 1024)
// ---------------------------------------------------------------------------
__global__ void k_final2(const float* __restrict__ vectors,
                         const float* __restrict__ noise,
                         float* __restrict__ out)
{
    int n = blockIdx.x * 1024 + threadIdx.x;  // 0..32767
    int b = n >> 5, d = n & 31;
    int midx = g_midx;
    float sz = g_sum[n];
    unsigned char code = g_code[b];
    float v2;
    if (code == 0) {
        v2 = vectors[n];
    } else {
        v2 = vectors[midx * DZ + d] + noise[n];
        if (code == 2) v2 += noise[midx * DZ + d];
    }
    float cntb = g_cnt[b];
    float mean = (cntb > 0.f) ? (sz / cntb) : v2;
    out[1 + n] = 0.99f * v2 + 0.01f * mean;
}

// ---------------------------------------------------------------------------
extern "C" void kernel_launch(void* const* d_in, const int* in_sizes, int n_in,
                              void* d_out, int out_size) {
    const float* x           = (const float*)d_in[0];
    const float* W_enc       = (const float*)d_in[1];
    const float* b_enc       = (const float*)d_in[2];
    const float* vectors     = (const float*)d_in[3];
    const float* W_dec       = (const float*)d_in[4];
    const float* b_dec       = (const float*)d_in[5];
    const float* assignments = (const float*)d_in[6];
    const float* noise       = (const float*)d_in[7];
    float* out = (float*)d_out;

    cudaFuncSetAttribute(k_main, cudaFuncAttributeMaxDynamicSharedMemorySize,
                         SMEM_MAIN);

    k_init<<<128, 256>>>(vectors, W_enc, W_dec);
    k_main<<<GRID_MAIN, 256, SMEM_MAIN>>>(x, b_enc, vectors, b_dec);
    k_final1<<<1, 1024>>>(assignments, out);
    k_final2<<<32, 1024>>>(vectors, noise, out);
}

// round 15
// speedup vs baseline: 1.0535x; 1.0535x over previous
#include <cuda_runtime.h>
#include <cuda_fp16.h>
#include <math.h>
#include <stdint.h>

typedef unsigned long long u64;
typedef unsigned int u32;

// Problem constants
#define NROWS 262144
#define DX 64
#define DZ 32
#define NB 1024
#define TR 256
#define GRID_MAIN (NROWS / TR)   // 1024
#define NCHUNK 128               // 1024 cols / 8
#define SZP 34                   // s_zf row stride (floats)

// Scratch globals
// Codebook B fragments (fp16-quantized v, HMMA m16n8k16 layout):
// [chunk 128][ktile 2][lane 32][reg 2] u32   (64 KB)
__device__ u32    g_bfrag[NCHUNK * 2 * 32 * 2];
// W_enc fragments fp16: [(kt*4+nt)*2+term][lane] ; term 0=hi 1=lo
__device__ uint2  g_wef[4 * 4 * 2 * 32];
// W_dec fragments fp16: [(kt*8+nt)*2+term][lane]
__device__ uint2  g_wdf[2 * 8 * 2 * 32];
__device__ float  g_hn[NB];            // 0.5*||fp16(v)||^2 (consistent w/ B)
__device__ float  g_sum[NB * DZ];      // global sum_z accumulator
__device__ float  g_cnt[NB];           // global count accumulator
__device__ unsigned char g_code[NB];
__device__ int    g_midx;
__device__ double g_recon;
__device__ double g_commit;

// pack two floats -> fp16x2 u32 (first element in low half)
__device__ __forceinline__ u32 pack_hf2(float f0, float f1) {
    __half2 h = __floats2half2_rn(f0, f1);
    return *(u32*)&h;
}
__device__ __forceinline__ float hf_hi(float f) {
    return __half2float(__float2half_rn(f));
}
__device__ __forceinline__ u32 pack_hlo2(float f0, float f1) {
    return pack_hf2(f0 - hf_hi(f0), f1 - hf_hi(f1));
}
// B-fragment load, L1-sticky
__device__ __forceinline__ uint2 ldg_b(const uint2* p) {
    uint2 v;
    asm volatile("ld.global.nc.L1::evict_last.v2.u32 {%0,%1}, [%2];"
                 : "=r"(v.x), "=r"(v.y) : "l"(p));
    return v;
}

#define MMA_F16(d, a, b) \
    asm volatile( \
        "mma.sync.aligned.m16n8k16.row.col.f32.f16.f16.f32 " \
        "{%0,%1,%2,%3},{%4,%5,%6,%7},{%8,%9},{%0,%1,%2,%3};" \
        : "+f"(d[0]), "+f"(d[1]), "+f"(d[2]), "+f"(d[3]) \
        : "r"(a[0]), "r"(a[1]), "r"(a[2]), "r"(a[3]), "r"(b[0]), "r"(b[1]))

// ---------------------------------------------------------------------------
// init: codebook/W fragments (fp16), hn on quantized codebook, zero accums.
// 32768 threads.
// ---------------------------------------------------------------------------
__global__ void k_init(const float* __restrict__ vectors,
                       const float* __restrict__ W_enc,
                       const float* __restrict__ W_dec) {
    int t = blockIdx.x * blockDim.x + threadIdx.x;  // 0..32767

    if (t < NCHUNK * 2 * 32) {           // codebook fragment (v_hi only)
        int lane  = t & 31;
        int tile  = (t >> 5) & 1;
        int chunk = t >> 6;
        int n  = chunk * 8 + (lane >> 2);
        int tt = lane & 3;
        int kbase = tile * 16 + 2 * tt;
        const float* vr = vectors + (size_t)n * DZ;
        g_bfrag[t * 2]     = pack_hf2(vr[kbase],     vr[kbase + 1]);
        g_bfrag[t * 2 + 1] = pack_hf2(vr[kbase + 8], vr[kbase + 9]);
    } else if (t < 8192 + 1024) {        // W_enc fragment
        int e = t - 8192;
        int lane = e & 31, term = (e >> 5) & 1, nt = (e >> 6) & 3, kt = e >> 8;
        int n = nt * 8 + (lane >> 2);
        int k = kt * 16 + 2 * (lane & 3);
        float a0 = W_enc[k * DZ + n],       a1 = W_enc[(k + 1) * DZ + n];
        float b0 = W_enc[(k + 8) * DZ + n], b1 = W_enc[(k + 9) * DZ + n];
        uint2 v;
        if (term == 0) { v.x = pack_hf2(a0, a1);  v.y = pack_hf2(b0, b1); }
        else           { v.x = pack_hlo2(a0, a1); v.y = pack_hlo2(b0, b1); }
        g_wef[e] = v;
    } else if (t < 8192 + 1024 + 2048) { // W_dec fragment
        int e = t - 8192 - 1024;
        int lane = e & 31, term = (e >> 5) & 1, nt = (e >> 6) & 7, kt = e >> 9;
        int n = nt * 8 + (lane >> 2);
        int k = kt * 16 + 2 * (lane & 3);
        float a0 = W_dec[k * DX + n],       a1 = W_dec[(k + 1) * DX + n];
        float b0 = W_dec[(k + 8) * DX + n], b1 = W_dec[(k + 9) * DX + n];
        uint2 v;
        if (term == 0) { v.x = pack_hf2(a0, a1);  v.y = pack_hf2(b0, b1); }
        else           { v.x = pack_hlo2(a0, a1); v.y = pack_hlo2(b0, b1); }
        g_wdf[e] = v;
    }

    g_sum[t] = 0.f;
    if (t < NB) {
        float s = 0.f;
#pragma unroll
        for (int d = 0; d < DZ; ++d) {
            float v = hf_hi(vectors[t * DZ + d]);   // quantized, matches B
            s = fmaf(v, v, s);
        }
        g_hn[t] = 0.5f * s;
        g_cnt[t] = 0.f;
    }
    if (t == 0) { g_recon = 0.0; g_commit = 0.0; }
}

// ---------------------------------------------------------------------------
// main fused kernel: 256 rows/CTA, each warp 32 rows (two m16 tiles).
// fp16 encoder MMA (2-term: x_hi.W_hi + x_hi.W_lo) -> fp16 scores MMA
// (z 2-term hi/lo, v 1-term, consistent hn — verified-stable path) ->
// argmin -> gather/atomics -> fp16 decoder MMA (2-term) -> losses.
// 256 threads, 2 CTAs/SM.  (1-term scores permanently abandoned: 4/4 fails.)
// ---------------------------------------------------------------------------
// smem float offsets:
#define SM_ZF   0                      // [256][34] 8704 (z, then q overlay)
#define SM_HN   8704                   // 1024
#define SM_BENC 9728                   // 32
#define SM_BDEC 9760                   // 64
#define SM_RIDX 9824                   // 256 (int)
#define SM_RED  10080                  // 16
#define SM_TOTAL_FLOATS 10096
#define SMEM_MAIN (SM_TOTAL_FLOATS * 4)

__global__ void __launch_bounds__(256, 2) k_main(
    const float* __restrict__ x, const float* __restrict__ b_enc,
    const float* __restrict__ vectors, const float* __restrict__ b_dec)
{
    extern __shared__ float sm[];
    float* s_zf   = sm + SM_ZF;
    float* s_hn   = sm + SM_HN;
    float* s_benc = sm + SM_BENC;
    float* s_bdec = sm + SM_BDEC;
    int*   s_ridx = (int*)(sm + SM_RIDX);
    float* s_red  = sm + SM_RED;

    const int tid  = threadIdx.x;
    const int wid  = tid >> 5;
    const int lane = tid & 31;
    const int g4   = lane >> 2;
    const int t4   = lane & 3;
    const int row0 = blockIdx.x * TR;
    const unsigned FULL = 0xFFFFFFFFu;

    // ---- biases + hn into smem ----
    for (int n = tid; n < NB; n += 256) s_hn[n] = g_hn[n];
    if (tid < DZ) s_benc[tid] = b_enc[tid];
    if (tid < DX) s_bdec[tid] = b_dec[tid];
    __syncthreads();

    // ---- encoder (per tile): z = x @ W_enc + b_enc via fp16 HMMA (2-term);
    //      scores A-fragments (fp16 hi/lo of z) built straight from regs ----
    u32 Ahi[2][2][4], Alo[2][2][4];   // [tile][kt][frag]
#pragma unroll
    for (int tile = 0; tile < 2; ++tile) {
        const int r0 = wid * 32 + tile * 16 + g4;
        const int r1 = r0 + 8;
        const float2* px0 = (const float2*)(x + (size_t)(row0 + r0) * DX);
        const float2* px1 = (const float2*)(x + (size_t)(row0 + r1) * DX);

        u32 XAhi[4][4];
#pragma unroll
        for (int kt = 0; kt < 4; ++kt) {
            int i0 = kt * 8 + t4;
            float2 x00 = px0[i0],     x10 = px1[i0];
            float2 x01 = px0[i0 + 4], x11 = px1[i0 + 4];
            XAhi[kt][0] = pack_hf2(x00.x, x00.y);
            XAhi[kt][1] = pack_hf2(x10.x, x10.y);
            XAhi[kt][2] = pack_hf2(x01.x, x01.y);
            XAhi[kt][3] = pack_hf2(x11.x, x11.y);
        }

        float zr[4][4];
#pragma unroll
        for (int nt = 0; nt < 4; ++nt) {
            int c0 = nt * 8 + 2 * t4;
            float2 be = *(const float2*)(s_benc + c0);
            float da[4] = {be.x, be.y, be.x, be.y};
            float db[4] = {0.f, 0.f, 0.f, 0.f};
#pragma unroll
            for (int kt = 0; kt < 4; ++kt) {
                uint2 bh = g_wef[((kt * 4 + nt) * 2 + 0) * 32 + lane];
                uint2 bl = g_wef[((kt * 4 + nt) * 2 + 1) * 32 + lane];
                u32 BH[2] = {bh.x, bh.y};
                u32 BL[2] = {bl.x, bl.y};
                MMA_F16(da, XAhi[kt], BH);   // x_hi . W_hi
                MMA_F16(db, XAhi[kt], BL);   // x_hi . W_lo
            }
#pragma unroll
            for (int i = 0; i < 4; ++i) zr[nt][i] = da[i] + db[i];
            *(float2*)(s_zf + r0 * SZP + c0) = make_float2(zr[nt][0], zr[nt][1]);
            *(float2*)(s_zf + r1 * SZP + c0) = make_float2(zr[nt][2], zr[nt][3]);
        }

        // scores A fragments (fp16 hi/lo of z): kt=0 <- nt0,1 ; kt=1 <- nt2,3
#pragma unroll
        for (int kt = 0; kt < 2; ++kt) {
            int n0 = kt * 2, n1 = kt * 2 + 1;
            Ahi[tile][kt][0] = pack_hf2(zr[n0][0], zr[n0][1]);
            Ahi[tile][kt][1] = pack_hf2(zr[n0][2], zr[n0][3]);
            Ahi[tile][kt][2] = pack_hf2(zr[n1][0], zr[n1][1]);
            Ahi[tile][kt][3] = pack_hf2(zr[n1][2], zr[n1][3]);
            Alo[tile][kt][0] = pack_hlo2(zr[n0][0], zr[n0][1]);
            Alo[tile][kt][1] = pack_hlo2(zr[n0][2], zr[n0][3]);
            Alo[tile][kt][2] = pack_hlo2(zr[n1][0], zr[n1][1]);
            Alo[tile][kt][3] = pack_hlo2(zr[n1][2], zr[n1][3]);
        }
    }
    __syncthreads();   // z visible block-wide (gather reads it later)

    // ---- scores: 8 HMMA per chunk (v 1-term, z 2-term, B reused) ----
    float best[4] = {-3.4e38f, -3.4e38f, -3.4e38f, -3.4e38f};
    int   bidx[4] = {0, 0, 0, 0};
    const uint2* bsrc = (const uint2*)g_bfrag + lane;

    uint2 n0 = ldg_b(bsrc), n1 = ldg_b(bsrc + 32);
    float2 hnv = *(const float2*)(s_hn + 2 * t4);

#pragma unroll 2
    for (int c = 0; c < NCHUNK; ++c) {
        u32 B0[2] = {n0.x, n0.y};
        u32 B1[2] = {n1.x, n1.y};
        float2 hn = hnv;
        if (c + 1 < NCHUNK) {
            const uint2* np = bsrc + (c + 1) * 64;
            n0 = ldg_b(np); n1 = ldg_b(np + 32);
            hnv = *(const float2*)(s_hn + (c + 1) * 8 + 2 * t4);
        }

        float da0[4] = {-hn.x, -hn.y, -hn.x, -hn.y};
        float db0[4] = {0.f, 0.f, 0.f, 0.f};
        float da1[4] = {-hn.x, -hn.y, -hn.x, -hn.y};
        float db1[4] = {0.f, 0.f, 0.f, 0.f};
        MMA_F16(da0, Ahi[0][0], B0);
        MMA_F16(db0, Ahi[0][1], B1);
        MMA_F16(da1, Ahi[1][0], B0);
        MMA_F16(db1, Ahi[1][1], B1);
        MMA_F16(da0, Alo[0][0], B0);
        MMA_F16(db0, Alo[0][1], B1);
        MMA_F16(da1, Alo[1][0], B0);
        MMA_F16(db1, Alo[1][1], B1);

        int col0 = c * 8 + 2 * t4;
#pragma unroll
        for (int tile = 0; tile < 2; ++tile) {
            const float* da = tile ? da1 : da0;
            const float* db = tile ? db1 : db0;
            float s0 = da[0] + db[0];
            float s1 = da[1] + db[1];
            float s2 = da[2] + db[2];
            float s3 = da[3] + db[3];
            bool c0 = s1 > s0;
            float v0 = c0 ? s1 : s0; int i0 = col0 + (int)c0;
            bool c1 = s3 > s2;
            float v1 = c1 ? s3 : s2; int i1 = col0 + (int)c1;
            if (v0 > best[tile * 2])     { best[tile * 2] = v0;     bidx[tile * 2] = i0; }
            if (v1 > best[tile * 2 + 1]) { best[tile * 2 + 1] = v1; bidx[tile * 2 + 1] = i1; }
        }
    }

    // ---- quad reduce (lanes sharing rows), lowest index on ties ----
#pragma unroll
    for (int i = 0; i < 4; ++i) {
        float bs = best[i]; int bi = bidx[i];
#pragma unroll
        for (int off = 1; off <= 2; off <<= 1) {
            float ob = __shfl_xor_sync(FULL, bs, off);
            int   oi = __shfl_xor_sync(FULL, bi, off);
            if (ob > bs || (ob == bs && oi < bi)) { bs = ob; bi = oi; }
        }
        if (t4 == 0) {
            int tile = i >> 1, half = i & 1;
            s_ridx[wid * 32 + tile * 16 + half * 8 + g4] = bi;
        }
    }
    __syncthreads();

    // ---- gather q + commitment + segment-sum atomics (z then q overlay) ---
    float commit = 0.f;
    {
        const int col = lane;
        const int rbg = wid * 32;
#pragma unroll
        for (int rr = 0; rr < 32; ++rr) {
            int r = rbg + rr;
            int b = s_ridx[r];
            float zz = s_zf[r * SZP + col];
            float q = vectors[(size_t)b * DZ + col];
            s_zf[r * SZP + col] = q;   // same thread, same address: overlay OK
            float df = q - zz;
            commit = fmaf(df, df, commit);
            atomicAdd(&g_sum[b * DZ + col], zz);
            if (col == 0) atomicAdd(&g_cnt[b], 1.f);
        }
    }
    __syncthreads();  // q complete block-wide

    // ---- decoder (per tile): mu = q @ W_dec + b_dec via fp16 HMMA (2-term);
    //      recon partial ----
    float recon = 0.f;
#pragma unroll
    for (int tile = 0; tile < 2; ++tile) {
        const int r0 = wid * 32 + tile * 16 + g4;
        const int r1 = r0 + 8;
        const float2* px0 = (const float2*)(x + (size_t)(row0 + r0) * DX);
        const float2* px1 = (const float2*)(x + (size_t)(row0 + r1) * DX);

        u32 QAhi[2][4];
#pragma unroll
        for (int kt = 0; kt < 2; ++kt) {
            int kb = kt * 16 + 2 * t4;
            float2 q00 = *(const float2*)(s_zf + r0 * SZP + kb);
            float2 q10 = *(const float2*)(s_zf + r1 * SZP + kb);
            float2 q01 = *(const float2*)(s_zf + r0 * SZP + kb + 8);
            float2 q11 = *(const float2*)(s_zf + r1 * SZP + kb + 8);
            QAhi[kt][0] = pack_hf2(q00.x, q00.y);
            QAhi[kt][1] = pack_hf2(q10.x, q10.y);
            QAhi[kt][2] = pack_hf2(q01.x, q01.y);
            QAhi[kt][3] = pack_hf2(q11.x, q11.y);
        }

#pragma unroll
        for (int nt = 0; nt < 8; ++nt) {
            int c0 = nt * 8 + 2 * t4;
            float2 bd = *(const float2*)(s_bdec + c0);
            float da[4] = {bd.x, bd.y, bd.x, bd.y};
            float db[4] = {0.f, 0.f, 0.f, 0.f};
#pragma unroll
            for (int kt = 0; kt < 2; ++kt) {
                uint2 bh = g_wdf[((kt * 8 + nt) * 2 + 0) * 32 + lane];
                uint2 bl = g_wdf[((kt * 8 + nt) * 2 + 1) * 32 + lane];
                u32 BH[2] = {bh.x, bh.y};
                u32 BL[2] = {bl.x, bl.y};
                MMA_F16(da, QAhi[kt], BH);   // q_hi . W_hi
                MMA_F16(db, QAhi[kt], BL);   // q_hi . W_lo
            }
            int i0 = nt * 4 + t4;
            float2 x0 = px0[i0];
            float2 x1 = px1[i0];
            float d0 = x0.x - (da[0] + db[0]);
            float d1 = x0.y - (da[1] + db[1]);
            float d2 = x1.x - (da[2] + db[2]);
            float d3 = x1.y - (da[3] + db[3]);
            recon = fmaf(d0, d0, recon);
            recon = fmaf(d1, d1, recon);
            recon = fmaf(d2, d2, recon);
            recon = fmaf(d3, d3, recon);
        }
    }

    // ---- block reduce losses -> double atomics ----
#pragma unroll
    for (int off = 16; off; off >>= 1) {
        commit += __shfl_xor_sync(FULL, commit, off);
        recon  += __shfl_xor_sync(FULL, recon, off);
    }
    if (lane == 0) { s_red[wid] = commit; s_red[8 + wid] = recon; }
    __syncthreads();
    if (tid == 0) {
        float cs = 0.f, rs = 0.f;
        for (int w = 0; w < 8; w++) { cs += s_red[w]; rs += s_red[8 + w]; }
        atomicAdd(&g_commit, (double)cs);
        atomicAdd(&g_recon,  (double)rs);
    }
}

// ---------------------------------------------------------------------------
// final1: aem, argmax, dead-code scan (fast path when none dead); loss + aem
// ---------------------------------------------------------------------------
__global__ void k_final1(const float* __restrict__ assignments,
                         float* __restrict__ out)
{
    __shared__ float s_aem[NB];
    __shared__ unsigned char s_na[NB];
    __shared__ unsigned char s_code[NB];
    __shared__ float s_rmax[32];
    __shared__ int   s_rmaxi[32];
    __shared__ int   s_maxidx;
    const unsigned FULL = 0xFFFFFFFFu;
    int tid = threadIdx.x;  // 1024 threads, tid == bin

    float c = g_cnt[tid];
    float ba = c * (1.0f / (float)NROWS);
    float aem = 0.99f * assignments[tid] + 0.01f * ba;
    s_aem[tid] = aem;
    int na = (aem * (float)NROWS) < 9.765625e-05f ? 1 : 0;
    s_na[tid] = (unsigned char)na;
    s_code[tid] = 0;

    float mv = c; int mi = tid;
#pragma unroll
    for (int off = 16; off; off >>= 1) {
        float ov = __shfl_xor_sync(FULL, mv, off);
        int   oi = __shfl_xor_sync(FULL, mi, off);
        if (ov > mv || (ov == mv && oi < mi)) { mv = ov; mi = oi; }
    }
    if ((tid & 31) == 0) { s_rmax[tid >> 5] = mv; s_rmaxi[tid >> 5] = mi; }
    int any_na = __syncthreads_or(na);
    if (tid == 0) {
        float m = s_rmax[0]; int midx = s_rmaxi[0];
        for (int w = 1; w < 32; w++) {
            if (s_rmax[w] > m || (s_rmax[w] == m && s_rmaxi[w] < midx)) {
                m = s_rmax[w]; midx = s_rmaxi[w];
            }
        }
        s_maxidx = midx;
        g_midx = midx;
    }
    __syncthreads();

    if (any_na) {
        if (tid == 0) {
            int midx = s_maxidx;
            bool maxRe = false;
            for (int i = NB - 1; i >= 0; --i) {
                if (s_na[i]) {
                    float na2 = s_aem[midx] * 0.5f;
                    s_code[i] = maxRe ? 2 : 1;
                    s_aem[i] = na2;
                    s_aem[midx] = na2;
                    if (i == midx) maxRe = true;
                }
            }
        }
        __syncthreads();
    }

    g_code[tid] = s_code[tid];
    out[1 + NB * DZ + tid] = s_aem[tid];

    if (tid == 0) {
        double recon = 0.5 * (g_recon / (double)NROWS)
                     + 32.0 * 1.8378770664093453;   // 0.5*d_x*log(2*pi)
        double commit = g_commit / ((double)NROWS * (double)DZ);
        out[0] = (float)(recon + 0.25 * commit);
    }
}

// ---------------------------------------------------------------------------
// final2: new_vectors (parallel, 32 blocks x 1024)
// ---------------------------------------------------------------------------
__global__ void k_final2(const float* __restrict__ vectors,
                         const float* __restrict__ noise,
                         float* __restrict__ out)
{
    int n = blockIdx.x * 1024 + threadIdx.x;  // 0..32767
    int b = n >> 5, d = n & 31;
    int midx = g_midx;
    float sz = g_sum[n];
    unsigned char code = g_code[b];
    float v2;
    if (code == 0) {
        v2 = vectors[n];
    } else {
        v2 = vectors[midx * DZ + d] + noise[n];
        if (code == 2) v2 += noise[midx * DZ + d];
    }
    float cntb = g_cnt[b];
    float mean = (cntb > 0.f) ? (sz / cntb) : v2;
    out[1 + n] = 0.99f * v2 + 0.01f * mean;
}

// ---------------------------------------------------------------------------
extern "C" void kernel_launch(void* const* d_in, const int* in_sizes, int n_in,
                              void* d_out, int out_size) {
    const float* x           = (const float*)d_in[0];
    const float* W_enc       = (const float*)d_in[1];
    const float* b_enc       = (const float*)d_in[2];
    const float* vectors     = (const float*)d_in[3];
    const float* W_dec       = (const float*)d_in[4];
    const float* b_dec       = (const float*)d_in[5];
    const float* assignments = (const float*)d_in[6];
    const float* noise       = (const float*)d_in[7];
    float* out = (float*)d_out;

    cudaFuncSetAttribute(k_main, cudaFuncAttributeMaxDynamicSharedMemorySize,
                         SMEM_MAIN);

    k_init<<<128, 256>>>(vectors, W_enc, W_dec);
    k_main<<<GRID_MAIN, 256, SMEM_MAIN>>>(x, b_enc, vectors, b_dec);
    k_final1<<<1, 1024>>>(assignments, out);
    k_final2<<<32, 1024>>>(vectors, noise, out);
}